// round 11
// baseline (speedup 1.0000x reference)
#include <cuda_runtime.h>
#include <math.h>

#define B_ 8
#define L_ 1024
#define D_ 256
#define U_ 256
#define NCHUNK 8
#define CHUNK 128

typedef unsigned long long ull;

// ---------------- scratch (device globals; no allocation allowed) ----------
__device__ float g_EW[D_ * U_];          // E @ Wx            (256 KB)
__device__ float g_rnorm[B_ * L_];       // 1/max(rowsum,eps) (32 KB)
__device__ float g_tp0[B_ * L_ * U_];    // (seq[:,0:128]@EW[0:128])*rnorm
__device__ float g_tp1[B_ * L_ * U_];    // (seq[:,128:256]@EW[128:256])*rnorm
__device__ float g_xp0[B_ * L_ * U_];    // G^T @ t partials  (8 MB each)
__device__ float g_xp1[B_ * L_ * U_];
__device__ float g_xp2[B_ * L_ * U_];
__device__ float g_xp3[B_ * L_ * U_];
__device__ int g_flags[B_][NCHUNK];      // producer->consumer chunk flags

// ---------------- packed f32x2 helpers (sm_103a) ----------------------------
__device__ __forceinline__ ull pk2(float lo, float hi) {
    ull r; asm("mov.b64 %0,{%1,%2};" : "=l"(r) : "f"(lo), "f"(hi)); return r;
}
__device__ __forceinline__ void ffma2(ull& d, ull a, ull b) {
    asm("fma.rn.f32x2 %0,%1,%2,%0;" : "+l"(d) : "l"(a), "l"(b));
}
__device__ __forceinline__ float2 up2(ull a) {
    float lo, hi; asm("mov.b64 {%0,%1},%2;" : "=f"(lo), "=f"(hi) : "l"(a));
    float2 r; r.x = lo; r.y = hi; return r;
}
// tanh(z) = 1 - 2/(1+exp(2z)) via MUFU (rel err ~1e-6; validated R3-R10)
__device__ __forceinline__ float fast_tanh(float z) {
    float t2 = z * 2.885390081777927f;  // 2*log2(e)
    float ex; asm("ex2.approx.f32 %0,%1;" : "=f"(ex) : "f"(t2));
    float den = ex + 1.0f;
    float rc; asm("rcp.approx.f32 %0,%1;" : "=f"(rc) : "f"(den));
    return fmaf(-2.0f, rc, 1.0f);
}

// ---------------- 0) zero chunk flags (graph-replay safe) -------------------
__global__ void zero_flags_kernel() {
    int i = threadIdx.x;
    if (i < B_ * NCHUNK) ((int*)g_flags)[i] = 0;
}

// ---------------- 1) rnorm[b,l] = 1 / max(sum_m graph[b,l,m], 1e-7) ---------
__global__ __launch_bounds__(256) void norm_kernel(const float* __restrict__ graph,
                                                   float* __restrict__ rnorm) {
    int warp = (blockIdx.x * blockDim.x + threadIdx.x) >> 5;
    int lane = threadIdx.x & 31;
    if (warp >= B_ * L_) return;
    const float4* row = (const float4*)(graph + (size_t)warp * L_);
    float s = 0.f;
#pragma unroll
    for (int i = lane; i < L_ / 4; i += 32) {
        float4 v = row[i];
        s += (v.x + v.y) + (v.z + v.w);
    }
#pragma unroll
    for (int o = 16; o; o >>= 1) s += __shfl_xor_sync(0xffffffffu, s, o);
    if (lane == 0) rnorm[warp] = 1.f / fmaxf(s, 1e-7f);
}

// ---------------- 2) GEMM NN: 128x128 tile, BK=16, optional K-split --------
__global__ __launch_bounds__(256) void gemm_nn(const float* __restrict__ A,
                                               const float* __restrict__ Bm,
                                               float* __restrict__ C0,
                                               float* __restrict__ C1,
                                               int K, int Ksub,
                                               const float* __restrict__ rowscale) {
    __shared__ float As[2][16][128];
    __shared__ float Bs[2][16][128];
    const int N = 256;
    const int m0 = blockIdx.y * 128, n0 = blockIdx.x * 128;
    const int kz = blockIdx.z;
    const int kbeg = kz * Ksub, kend = kbeg + Ksub;
    float* C = kz ? C1 : C0;
    const int t = threadIdx.x;
    const int tx = t & 15, ty = t >> 4;

    ull acc[8][4];
#pragma unroll
    for (int i = 0; i < 8; i++)
#pragma unroll
        for (int j = 0; j < 4; j++) acc[i][j] = 0ull;

    int am[2], akg[2], bkk[2], bng[2];
#pragma unroll
    for (int i = 0; i < 2; i++) {
        int f4 = t + i * 256;
        am[i] = f4 >> 2; akg[i] = f4 & 3;
        bkk[i] = f4 >> 5; bng[i] = f4 & 31;
    }

    float4 ra[2], rb[2];
#pragma unroll
    for (int i = 0; i < 2; i++) {
        ra[i] = *(const float4*)(A + (size_t)(m0 + am[i]) * K + kbeg + akg[i] * 4);
        rb[i] = *(const float4*)(Bm + (size_t)(kbeg + bkk[i]) * N + n0 + bng[i] * 4);
    }

    int cur = 0;
    for (int k0 = kbeg; k0 < kend; k0 += 16) {
#pragma unroll
        for (int i = 0; i < 2; i++) {
            As[cur][akg[i] * 4 + 0][am[i]] = ra[i].x;
            As[cur][akg[i] * 4 + 1][am[i]] = ra[i].y;
            As[cur][akg[i] * 4 + 2][am[i]] = ra[i].z;
            As[cur][akg[i] * 4 + 3][am[i]] = ra[i].w;
            *(float4*)&Bs[cur][bkk[i]][bng[i] * 4] = rb[i];
        }
        __syncthreads();
        if (k0 + 16 < kend) {
#pragma unroll
            for (int i = 0; i < 2; i++) {
                ra[i] = *(const float4*)(A + (size_t)(m0 + am[i]) * K + k0 + 16 + akg[i] * 4);
                rb[i] = *(const float4*)(Bm + (size_t)(k0 + 16 + bkk[i]) * N + n0 + bng[i] * 4);
            }
        }
#pragma unroll
        for (int kk = 0; kk < 16; kk++) {
            float4 a0 = *(float4*)&As[cur][kk][ty * 8];
            float4 a1 = *(float4*)&As[cur][kk][ty * 8 + 4];
            float4 b0 = *(float4*)&Bs[cur][kk][tx * 8];
            float4 b1 = *(float4*)&Bs[cur][kk][tx * 8 + 4];
            ull bp0 = pk2(b0.x, b0.y), bp1 = pk2(b0.z, b0.w);
            ull bp2 = pk2(b1.x, b1.y), bp3 = pk2(b1.z, b1.w);
            float av[8] = {a0.x, a0.y, a0.z, a0.w, a1.x, a1.y, a1.z, a1.w};
#pragma unroll
            for (int i = 0; i < 8; i++) {
                ull ad = pk2(av[i], av[i]);
                ffma2(acc[i][0], ad, bp0);
                ffma2(acc[i][1], ad, bp1);
                ffma2(acc[i][2], ad, bp2);
                ffma2(acc[i][3], ad, bp3);
            }
        }
        cur ^= 1;
    }
#pragma unroll
    for (int i = 0; i < 8; i++) {
        int row = m0 + ty * 8 + i;
        float sc = rowscale ? rowscale[row] : 1.f;
        float2 v0 = up2(acc[i][0]), v1 = up2(acc[i][1]);
        float2 v2 = up2(acc[i][2]), v3 = up2(acc[i][3]);
        float4 o0 = make_float4(v0.x * sc, v0.y * sc, v1.x * sc, v1.y * sc);
        float4 o1 = make_float4(v2.x * sc, v2.y * sc, v3.x * sc, v3.y * sc);
        *(float4*)(C + (size_t)row * N + n0 + tx * 8) = o0;
        *(float4*)(C + (size_t)row * N + n0 + tx * 8 + 4) = o1;
    }
}

// ---------------- fused kernel: 4 dual-batch scan CTAs + 512 gemm CTAs ------
// Scan CTA b2 (0..3) runs batches 2*b2 and 2*b2+1, sharing weight loads.
// gemm CTA gid = bid-4: nt=gid&1, bks=(gid>>1)&31 (b*4+ks), mchunk=gid>>6.
#define RF_PAIRS 24
#define SM_PAIRS 8
#define WS_ULLS (SM_PAIRS * 4 * 4 * 64)          // 8192 ull = 64 KB
#define OFF_PART (WS_ULLS * 8)                   // 2 batches x 1024 floats
#define OFF_HB (OFF_PART + 2 * 1024 * 4)         // 2 batches x 2 bufs x 256
#define SCAN_SMEM_BYTES (OFF_HB + 4 * 256 * 4)   // 64K + 8K + 4K = 76 KB

__global__ __launch_bounds__(256) void fused_kernel(
    const float* __restrict__ graph,
    const float* __restrict__ tp0, const float* __restrict__ tp1,
    const float* __restrict__ Wh, const float* __restrict__ bias,
    float* __restrict__ xq0, float* __restrict__ xq1,
    float* __restrict__ xq2, float* __restrict__ xq3,
    float* __restrict__ out) {
    extern __shared__ unsigned char smraw[];
    const int tid = threadIdx.x;

    if (blockIdx.x >= 4) {
        // ================= gemm_tn path (K-split 4, identical to R9) ========
        float (*As)[16][128] = (float (*)[16][128])smraw;
        float (*Bs)[16][128] = (float (*)[16][128])(smraw + 2 * 16 * 128 * 4);
        const int gid = blockIdx.x - 4;
        const int nt = gid & 1, bks = (gid >> 1) & 31, mchunk = gid >> 6;
        const int b = bks >> 2, ks = bks & 3;
        const int kbeg = ks * (L_ / 4), kend = kbeg + (L_ / 4);
        const int N = 256, lda = L_;
        const float* Ab = graph + (size_t)b * L_ * L_;
        const float* Bb0 = tp0 + (size_t)b * L_ * U_;
        const float* Bb1 = tp1 + (size_t)b * L_ * U_;
        float* Cs = (ks == 0) ? xq0 : (ks == 1) ? xq1 : (ks == 2) ? xq2 : xq3;
        float* C = Cs + (size_t)b * L_ * U_;
        const int m0 = mchunk * 128, n0 = nt * 128;
        const int tx = tid & 15, ty = tid >> 4;

        ull acc[8][4];
#pragma unroll
        for (int i = 0; i < 8; i++)
#pragma unroll
            for (int j = 0; j < 4; j++) acc[i][j] = 0ull;

        int kk_[2], g_[2];
#pragma unroll
        for (int i = 0; i < 2; i++) {
            int f4 = tid + i * 256;
            kk_[i] = f4 >> 5; g_[i] = f4 & 31;
        }

        float4 ra[2], rb0[2], rb1[2];
#pragma unroll
        for (int i = 0; i < 2; i++) {
            size_t ko = (size_t)(kbeg + kk_[i]);
            ra[i] = *(const float4*)(Ab + ko * lda + m0 + g_[i] * 4);
            rb0[i] = *(const float4*)(Bb0 + ko * N + n0 + g_[i] * 4);
            rb1[i] = *(const float4*)(Bb1 + ko * N + n0 + g_[i] * 4);
        }

        int cur = 0;
        for (int k0 = kbeg; k0 < kend; k0 += 16) {
#pragma unroll
            for (int i = 0; i < 2; i++) {
                *(float4*)&As[cur][kk_[i]][g_[i] * 4] = ra[i];
                float4 s = make_float4(rb0[i].x + rb1[i].x, rb0[i].y + rb1[i].y,
                                       rb0[i].z + rb1[i].z, rb0[i].w + rb1[i].w);
                *(float4*)&Bs[cur][kk_[i]][g_[i] * 4] = s;
            }
            __syncthreads();
            if (k0 + 16 < kend) {
#pragma unroll
                for (int i = 0; i < 2; i++) {
                    size_t ko = (size_t)(k0 + 16 + kk_[i]);
                    ra[i] = *(const float4*)(Ab + ko * lda + m0 + g_[i] * 4);
                    rb0[i] = *(const float4*)(Bb0 + ko * N + n0 + g_[i] * 4);
                    rb1[i] = *(const float4*)(Bb1 + ko * N + n0 + g_[i] * 4);
                }
            }
#pragma unroll
            for (int kk = 0; kk < 16; kk++) {
                float4 a0 = *(float4*)&As[cur][kk][ty * 8];
                float4 a1 = *(float4*)&As[cur][kk][ty * 8 + 4];
                float4 b0 = *(float4*)&Bs[cur][kk][tx * 8];
                float4 b1 = *(float4*)&Bs[cur][kk][tx * 8 + 4];
                ull bp0 = pk2(b0.x, b0.y), bp1 = pk2(b0.z, b0.w);
                ull bp2 = pk2(b1.x, b1.y), bp3 = pk2(b1.z, b1.w);
                float av[8] = {a0.x, a0.y, a0.z, a0.w, a1.x, a1.y, a1.z, a1.w};
#pragma unroll
                for (int i = 0; i < 8; i++) {
                    ull ad = pk2(av[i], av[i]);
                    ffma2(acc[i][0], ad, bp0);
                    ffma2(acc[i][1], ad, bp1);
                    ffma2(acc[i][2], ad, bp2);
                    ffma2(acc[i][3], ad, bp3);
                }
            }
            cur ^= 1;
        }
#pragma unroll
        for (int i = 0; i < 8; i++) {
            int row = m0 + ty * 8 + i;
            float2 v0 = up2(acc[i][0]), v1 = up2(acc[i][1]);
            float2 v2 = up2(acc[i][2]), v3 = up2(acc[i][3]);
            float4 o0 = make_float4(v0.x, v0.y, v1.x, v1.y);
            float4 o1 = make_float4(v2.x, v2.y, v3.x, v3.y);
            *(float4*)(C + (size_t)row * N + n0 + tx * 8) = o0;
            *(float4*)(C + (size_t)row * N + n0 + tx * 8 + 4) = o1;
        }
        __threadfence();
        __syncthreads();
        if (tid == 0) atomicAdd(&g_flags[b][mchunk], 1);
        return;
    }

    // ============ dual-batch scan: weights loaded once, used twice ==========
    ull* ws = (ull*)smraw;                           // 64 KB SMEM weights
    float* part = (float*)(smraw + OFF_PART);        // 2 x 1024 partials
    float* hb0 = (float*)(smraw + OFF_HB);           // batch0 h (2 x 256)
    float* hb1 = hb0 + 512;                          // batch1 h (2 x 256)

    const int b0 = blockIdx.x * 2;
    const int w = tid >> 5, l = tid & 31;
    const int ks = w >> 1, oh = w & 1;
    const int u0 = oh * 128 + l * 4;
    const size_t BOFF = (size_t)L_ * U_;             // batch stride in floats

    // ws[ps*1024 + ks*256 + j*64 + oh*32 + l] = pair(k,k+1), k = ks*64+2*(24+ps)
    for (int idx = tid; idx < WS_ULLS; idx += 256) {
        int e = idx >> 6, r = idx & 63;
        int ps = e >> 4, ksf = (e >> 2) & 3, jf = e & 3;
        int ohf = r >> 5, lf = r & 31;
        int uf = ohf * 128 + lf * 4 + jf;
        int kf = ksf * 64 + 2 * (RF_PAIRS + ps);
        ws[idx] = pk2(Wh[kf * U_ + uf], Wh[(kf + 1) * U_ + uf]);
    }

    ull wreg[4][RF_PAIRS];
#pragma unroll
    for (int j = 0; j < 4; j++)
#pragma unroll
        for (int p = 0; p < RF_PAIRS; p++) {
            int k = ks * 64 + 2 * p;
            wreg[j][p] = pk2(Wh[k * U_ + u0 + j], Wh[(k + 1) * U_ + u0 + j]);
        }

    hb0[tid] = 0.f; hb0[256 + tid] = 0.f;
    hb1[tid] = 0.f; hb1[256 + tid] = 0.f;
    const float bv = bias[tid];
    __syncthreads();

    const float* xp0 = xq0 + (size_t)b0 * BOFF + tid;
    const float* xp1 = xq1 + (size_t)b0 * BOFF + tid;
    const float* xp2 = xq2 + (size_t)b0 * BOFF + tid;
    const float* xp3 = xq3 + (size_t)b0 * BOFF + tid;
    float* op0 = out + (size_t)b0 * BOFF + tid;
    int cur = 0;

    const ull* wsp = ws + ks * 256 + oh * 32 + l;
    volatile int* fl0 = &g_flags[b0][0];
    volatile int* fl1 = &g_flags[b0 + 1][0];

    for (int c = 0; c < NCHUNK; c++) {
        if (tid == 0) {
            while (fl0[c] < 8) { }
            while (fl1[c] < 8) { }
        }
        __syncthreads();
        __threadfence();  // acquire: pair with producers' release fences

        for (int si = 0; si < CHUNK; si++) {
            int s = c * CHUNK + si;
            size_t xo = (size_t)s * U_;
            float xa0 = xp0[xo], xb0_ = xp1[xo], xc0 = xp2[xo], xd0 = xp3[xo];
            float xa1 = xp0[xo + BOFF], xb1 = xp1[xo + BOFF];
            float xc1 = xp2[xo + BOFF], xd1 = xp3[xo + BOFF];

            const ulonglong2* hA = (const ulonglong2*)(hb0 + cur * 256 + ks * 64);
            const ulonglong2* hB = (const ulonglong2*)(hb1 + cur * 256 + ks * 64);
            ull aA0 = 0ull, aA1 = 0ull, aA2 = 0ull, aA3 = 0ull;
            ull aB0 = 0ull, aB1 = 0ull, aB2 = 0ull, aB3 = 0ull;

            // SMEM-weight section FIRST (R9 win): each weight feeds BOTH batches
#pragma unroll
            for (int ps2 = 0; ps2 < 4; ps2++) {      // pairs 24..31
                ulonglong2 hva = hA[12 + ps2];
                ulonglong2 hvb = hB[12 + ps2];
                int p0 = 2 * ps2, p1 = 2 * ps2 + 1;
                ull w0 = wsp[p0 * 1024 + 0 * 64];
                ull w1 = wsp[p0 * 1024 + 1 * 64];
                ull w2 = wsp[p0 * 1024 + 2 * 64];
                ull w3 = wsp[p0 * 1024 + 3 * 64];
                ffma2(aA0, hva.x, w0); ffma2(aB0, hvb.x, w0);
                ffma2(aA1, hva.x, w1); ffma2(aB1, hvb.x, w1);
                ffma2(aA2, hva.x, w2); ffma2(aB2, hvb.x, w2);
                ffma2(aA3, hva.x, w3); ffma2(aB3, hvb.x, w3);
                ull v0 = wsp[p1 * 1024 + 0 * 64];
                ull v1 = wsp[p1 * 1024 + 1 * 64];
                ull v2 = wsp[p1 * 1024 + 2 * 64];
                ull v3 = wsp[p1 * 1024 + 3 * 64];
                ffma2(aA0, hva.y, v0); ffma2(aB0, hvb.y, v0);
                ffma2(aA1, hva.y, v1); ffma2(aB1, hvb.y, v1);
                ffma2(aA2, hva.y, v2); ffma2(aB2, hvb.y, v2);
                ffma2(aA3, hva.y, v3); ffma2(aB3, hvb.y, v3);
            }
            // RF section: pairs 0..23
#pragma unroll
            for (int q = 0; q < 12; q++) {
                ulonglong2 hva = hA[q];
                ulonglong2 hvb = hB[q];
                ffma2(aA0, hva.x, wreg[0][2 * q]);
                ffma2(aA1, hva.x, wreg[1][2 * q]);
                ffma2(aA2, hva.x, wreg[2][2 * q]);
                ffma2(aA3, hva.x, wreg[3][2 * q]);
                ffma2(aA0, hva.y, wreg[0][2 * q + 1]);
                ffma2(aA1, hva.y, wreg[1][2 * q + 1]);
                ffma2(aA2, hva.y, wreg[2][2 * q + 1]);
                ffma2(aA3, hva.y, wreg[3][2 * q + 1]);
                ffma2(aB0, hvb.x, wreg[0][2 * q]);
                ffma2(aB1, hvb.x, wreg[1][2 * q]);
                ffma2(aB2, hvb.x, wreg[2][2 * q]);
                ffma2(aB3, hvb.x, wreg[3][2 * q]);
                ffma2(aB0, hvb.y, wreg[0][2 * q + 1]);
                ffma2(aB1, hvb.y, wreg[1][2 * q + 1]);
                ffma2(aB2, hvb.y, wreg[2][2 * q + 1]);
                ffma2(aB3, hvb.y, wreg[3][2 * q + 1]);
            }

            float2 vA0 = up2(aA0), vA1 = up2(aA1), vA2 = up2(aA2), vA3 = up2(aA3);
            float2 vB0 = up2(aB0), vB1 = up2(aB1), vB2 = up2(aB2), vB3 = up2(aB3);
            *(float4*)&part[ks * 256 + u0] =
                make_float4(vA0.x + vA0.y, vA1.x + vA1.y, vA2.x + vA2.y, vA3.x + vA3.y);
            *(float4*)&part[1024 + ks * 256 + u0] =
                make_float4(vB0.x + vB0.y, vB1.x + vB1.y, vB2.x + vB2.y, vB3.x + vB3.y);
            float xv0 = ((xa0 + xb0_) + (xc0 + xd0)) + bv;
            float xv1 = ((xa1 + xb1) + (xc1 + xd1)) + bv;
            __syncthreads();

            float z0 = part[tid] + part[256 + tid] + part[512 + tid] +
                       part[768 + tid] + xv0;
            float z1 = part[1024 + tid] + part[1280 + tid] + part[1536 + tid] +
                       part[1792 + tid] + xv1;
            float h0 = fast_tanh(z0);
            float h1 = fast_tanh(z1);
            int nxt = cur ^ 1;
            hb0[nxt * 256 + tid] = h0;
            hb1[nxt * 256 + tid] = h1;
            op0[xo] = h0;
            op0[xo + BOFF] = h1;
            cur = nxt;
            __syncthreads();
        }
    }
}

// ---------------- launch --------------------------------------------------
extern "C" void kernel_launch(void* const* d_in, const int* in_sizes, int n_in,
                              void* d_out, int out_size) {
    const float* seq = (const float*)d_in[0];    // (8,1024,256)
    const float* graph = (const float*)d_in[1];  // (8,1024,1024)
    const float* E = (const float*)d_in[2];      // (256,256)
    const float* Wx = (const float*)d_in[3];     // (256,256)
    const float* Wh = (const float*)d_in[4];     // (256,256)
    const float* bias = (const float*)d_in[5];   // (256,)
    float* out = (float*)d_out;                  // (8,1024,256)

    float *ew, *rn, *t0, *t1, *x0, *x1, *x2, *x3;
    cudaGetSymbolAddress((void**)&ew, g_EW);
    cudaGetSymbolAddress((void**)&rn, g_rnorm);
    cudaGetSymbolAddress((void**)&t0, g_tp0);
    cudaGetSymbolAddress((void**)&t1, g_tp1);
    cudaGetSymbolAddress((void**)&x0, g_xp0);
    cudaGetSymbolAddress((void**)&x1, g_xp1);
    cudaGetSymbolAddress((void**)&x2, g_xp2);
    cudaGetSymbolAddress((void**)&x3, g_xp3);

    zero_flags_kernel<<<1, 64>>>();
    norm_kernel<<<(B_ * L_) / 8, 256>>>(graph, rn);
    // EW = E @ Wx (256x256x256, no K-split: Ksub = 256)
    gemm_nn<<<dim3(2, 2, 1), 256>>>(E, Wx, ew, ew, 256, 256, nullptr);
    // t partials: K-split 2 (Ksub = 128), grid z selects half + buffer
    gemm_nn<<<dim3(2, 64, 2), 256>>>(seq, ew, t0, t1, 256, 128, rn);
    // fused: 4 dual-batch scan CTAs + 512 gemm_tn CTAs
    cudaFuncSetAttribute(fused_kernel, cudaFuncAttributeMaxDynamicSharedMemorySize,
                         SCAN_SMEM_BYTES);
    fused_kernel<<<4 + 512, 256, SCAN_SMEM_BYTES>>>(graph, t0, t1, Wh, bias,
                                                    x0, x1, x2, x3, out);
}

// round 12
// speedup vs baseline: 1.5417x; 1.5417x over previous
#include <cuda_runtime.h>
#include <math.h>

#define B_ 8
#define L_ 1024
#define D_ 256
#define U_ 256
#define NCHUNK 8
#define CHUNK 128

typedef unsigned long long ull;

// ---------------- scratch (device globals; no allocation allowed) ----------
__device__ float g_EW[D_ * U_];          // E @ Wx            (256 KB)
__device__ float g_rnorm[B_ * L_];       // 1/max(rowsum,eps)
__device__ float g_tp0[B_ * L_ * U_];    // seq[:,0:128]@EW[0:128]   (unscaled)
__device__ float g_tp1[B_ * L_ * U_];    // seq[:,128:256]@EW[128:256]
__device__ float g_xp0[B_ * L_ * U_];    // G^T @ t partials  (8 MB each)
__device__ float g_xp1[B_ * L_ * U_];
__device__ float g_xp2[B_ * L_ * U_];
__device__ float g_xp3[B_ * L_ * U_];
__device__ int g_flags[B_][NCHUNK];      // xproj chunk flags (count 8)
__device__ int g_tfl[B_ * 4];            // t ready per (b,ks) (count 8)
__device__ int g_nfl[B_ * 4];            // rn ready per (b,ks) (count 1)

// ---------------- packed f32x2 helpers (sm_103a) ----------------------------
__device__ __forceinline__ ull pk2(float lo, float hi) {
    ull r; asm("mov.b64 %0,{%1,%2};" : "=l"(r) : "f"(lo), "f"(hi)); return r;
}
__device__ __forceinline__ void ffma2(ull& d, ull a, ull b) {
    asm("fma.rn.f32x2 %0,%1,%2,%0;" : "+l"(d) : "l"(a), "l"(b));
}
__device__ __forceinline__ float2 up2(ull a) {
    float lo, hi; asm("mov.b64 {%0,%1},%2;" : "=f"(lo), "=f"(hi) : "l"(a));
    float2 r; r.x = lo; r.y = hi; return r;
}
// tanh(z) = 1 - 2/(1+exp(2z)) via MUFU (rel err ~1e-6; validated R3-R11)
__device__ __forceinline__ float fast_tanh(float z) {
    float t2 = z * 2.885390081777927f;  // 2*log2(e)
    float ex; asm("ex2.approx.f32 %0,%1;" : "=f"(ex) : "f"(t2));
    float den = ex + 1.0f;
    float rc; asm("rcp.approx.f32 %0,%1;" : "=f"(rc) : "f"(den));
    return fmaf(-2.0f, rc, 1.0f);
}

// ---------------- 0) zero all flags (graph-replay safe) ---------------------
__global__ void zero_flags_kernel() {
    int i = threadIdx.x;
    if (i < B_ * NCHUNK) ((int*)g_flags)[i] = 0;
    if (i < B_ * 4) { g_tfl[i] = 0; g_nfl[i] = 0; }
}

// ---------------- 1) GEMM NN standalone (EW = E @ Wx only) ------------------
__global__ __launch_bounds__(256) void gemm_nn(const float* __restrict__ A,
                                               const float* __restrict__ Bm,
                                               float* __restrict__ C, int K,
                                               const float* __restrict__ rowscale) {
    __shared__ float As[2][16][128];
    __shared__ float Bs[2][16][128];
    const int N = 256;
    const int m0 = blockIdx.y * 128, n0 = blockIdx.x * 128;
    const int t = threadIdx.x;
    const int tx = t & 15, ty = t >> 4;

    ull acc[8][4];
#pragma unroll
    for (int i = 0; i < 8; i++)
#pragma unroll
        for (int j = 0; j < 4; j++) acc[i][j] = 0ull;

    int am[2], akg[2], bkk[2], bng[2];
#pragma unroll
    for (int i = 0; i < 2; i++) {
        int f4 = t + i * 256;
        am[i] = f4 >> 2; akg[i] = f4 & 3;
        bkk[i] = f4 >> 5; bng[i] = f4 & 31;
    }

    float4 ra[2], rb[2];
#pragma unroll
    for (int i = 0; i < 2; i++) {
        ra[i] = *(const float4*)(A + (size_t)(m0 + am[i]) * K + akg[i] * 4);
        rb[i] = *(const float4*)(Bm + (size_t)bkk[i] * N + n0 + bng[i] * 4);
    }

    int cur = 0;
    for (int k0 = 0; k0 < K; k0 += 16) {
#pragma unroll
        for (int i = 0; i < 2; i++) {
            As[cur][akg[i] * 4 + 0][am[i]] = ra[i].x;
            As[cur][akg[i] * 4 + 1][am[i]] = ra[i].y;
            As[cur][akg[i] * 4 + 2][am[i]] = ra[i].z;
            As[cur][akg[i] * 4 + 3][am[i]] = ra[i].w;
            *(float4*)&Bs[cur][bkk[i]][bng[i] * 4] = rb[i];
        }
        __syncthreads();
        if (k0 + 16 < K) {
#pragma unroll
            for (int i = 0; i < 2; i++) {
                ra[i] = *(const float4*)(A + (size_t)(m0 + am[i]) * K + k0 + 16 + akg[i] * 4);
                rb[i] = *(const float4*)(Bm + (size_t)(k0 + 16 + bkk[i]) * N + n0 + bng[i] * 4);
            }
        }
#pragma unroll
        for (int kk = 0; kk < 16; kk++) {
            float4 a0 = *(float4*)&As[cur][kk][ty * 8];
            float4 a1 = *(float4*)&As[cur][kk][ty * 8 + 4];
            float4 b0 = *(float4*)&Bs[cur][kk][tx * 8];
            float4 b1 = *(float4*)&Bs[cur][kk][tx * 8 + 4];
            ull bp0 = pk2(b0.x, b0.y), bp1 = pk2(b0.z, b0.w);
            ull bp2 = pk2(b1.x, b1.y), bp3 = pk2(b1.z, b1.w);
            float av[8] = {a0.x, a0.y, a0.z, a0.w, a1.x, a1.y, a1.z, a1.w};
#pragma unroll
            for (int i = 0; i < 8; i++) {
                ull ad = pk2(av[i], av[i]);
                ffma2(acc[i][0], ad, bp0);
                ffma2(acc[i][1], ad, bp1);
                ffma2(acc[i][2], ad, bp2);
                ffma2(acc[i][3], ad, bp3);
            }
        }
        cur ^= 1;
    }
#pragma unroll
    for (int i = 0; i < 8; i++) {
        int row = m0 + ty * 8 + i;
        float sc = rowscale ? rowscale[row] : 1.f;
        float2 v0 = up2(acc[i][0]), v1 = up2(acc[i][1]);
        float2 v2 = up2(acc[i][2]), v3 = up2(acc[i][3]);
        float4 o0 = make_float4(v0.x * sc, v0.y * sc, v1.x * sc, v1.y * sc);
        float4 o1 = make_float4(v2.x * sc, v2.y * sc, v3.x * sc, v3.y * sc);
        *(float4*)(C + (size_t)row * N + n0 + tx * 8) = o0;
        *(float4*)(C + (size_t)row * N + n0 + tx * 8 + 4) = o1;
    }
}

// ---------------- fused pipeline kernel --------------------------------------
// blockIdx roles:
//   [0, 8)     scan CTAs (one per batch)      — waits on g_flags chunks
//   [8, 40)    norm CTAs (b*4+ks)             — produces g_rnorm + g_nfl
//   [40, 296)  t' CTAs (seq@EW K-split 2)     — produces tp0/tp1 + g_tfl
//   [296, 808) gemm_tn CTAs (K-split 4)       — waits tfl+nfl, produces xq*
#define RF_PAIRS 26
#define SM_PAIRS 6
#define WS2_ELEMS (SM_PAIRS * 2 * 256)           // 3072 ulonglong2 = 48 KB
#define OFF_PART (WS2_ELEMS * 16)
#define OFF_HB (OFF_PART + 4 * 256 * 4)
#define SCAN_SMEM_BYTES (OFF_HB + 2 * 256 * 4)   // 48K + 4K + 2K = 54 KB

__global__ __launch_bounds__(256) void fused_kernel(
    const float* __restrict__ graph, const float* __restrict__ seq,
    const float* __restrict__ ewp,
    const float* __restrict__ Wh, const float* __restrict__ bias,
    float* __restrict__ rn,
    float* __restrict__ tq0, float* __restrict__ tq1,
    float* __restrict__ xq0, float* __restrict__ xq1,
    float* __restrict__ xq2, float* __restrict__ xq3,
    float* __restrict__ out) {
    extern __shared__ unsigned char smraw[];
    const int tid = threadIdx.x;
    const int bid = blockIdx.x;

    if (bid >= 8 && bid < 40) {
        // ================= norm role: rows [ks*256, +256) of batch b ========
        const int nb = bid - 8;
        const int b = nb >> 2, ks4 = nb & 3;
        const int w = tid >> 5, l = tid & 31;
        const float* gb = graph + (size_t)b * L_ * L_ + (size_t)ks4 * 256 * L_;
        for (int r = w; r < 256; r += 8) {
            const float4* row = (const float4*)(gb + (size_t)r * L_);
            float s = 0.f;
#pragma unroll
            for (int i = l; i < L_ / 4; i += 32) {
                float4 v = row[i];
                s += (v.x + v.y) + (v.z + v.w);
            }
#pragma unroll
            for (int o = 16; o; o >>= 1) s += __shfl_xor_sync(0xffffffffu, s, o);
            if (l == 0) rn[b * L_ + ks4 * 256 + r] = 1.f / fmaxf(s, 1e-7f);
        }
        __threadfence();
        __syncthreads();
        if (tid == 0) atomicAdd(&g_nfl[nb], 1);
        return;
    }

    if (bid >= 40 && bid < 296) {
        // ================= t' role: seq @ EW, K-split 2, unscaled ===========
        float (*As)[16][128] = (float (*)[16][128])smraw;
        float (*Bs)[16][128] = (float (*)[16][128])(smraw + 2 * 16 * 128 * 4);
        const int gid = bid - 40;
        const int nt = gid & 1, mt = (gid >> 1) & 63, kz = gid >> 7;
        const int K = 256, N = 256;
        const int m0 = mt * 128, n0 = nt * 128;
        const int kbeg = kz * 128, kend = kbeg + 128;
        float* C = kz ? tq1 : tq0;
        const int tx = tid & 15, ty = tid >> 4;

        ull acc[8][4];
#pragma unroll
        for (int i = 0; i < 8; i++)
#pragma unroll
            for (int j = 0; j < 4; j++) acc[i][j] = 0ull;

        int am[2], akg[2], bkk[2], bng[2];
#pragma unroll
        for (int i = 0; i < 2; i++) {
            int f4 = tid + i * 256;
            am[i] = f4 >> 2; akg[i] = f4 & 3;
            bkk[i] = f4 >> 5; bng[i] = f4 & 31;
        }

        float4 ra[2], rb[2];
#pragma unroll
        for (int i = 0; i < 2; i++) {
            ra[i] = *(const float4*)(seq + (size_t)(m0 + am[i]) * K + kbeg + akg[i] * 4);
            rb[i] = *(const float4*)(ewp + (size_t)(kbeg + bkk[i]) * N + n0 + bng[i] * 4);
        }

        int cur = 0;
        for (int k0 = kbeg; k0 < kend; k0 += 16) {
#pragma unroll
            for (int i = 0; i < 2; i++) {
                As[cur][akg[i] * 4 + 0][am[i]] = ra[i].x;
                As[cur][akg[i] * 4 + 1][am[i]] = ra[i].y;
                As[cur][akg[i] * 4 + 2][am[i]] = ra[i].z;
                As[cur][akg[i] * 4 + 3][am[i]] = ra[i].w;
                *(float4*)&Bs[cur][bkk[i]][bng[i] * 4] = rb[i];
            }
            __syncthreads();
            if (k0 + 16 < kend) {
#pragma unroll
                for (int i = 0; i < 2; i++) {
                    ra[i] = *(const float4*)(seq + (size_t)(m0 + am[i]) * K + k0 + 16 + akg[i] * 4);
                    rb[i] = *(const float4*)(ewp + (size_t)(k0 + 16 + bkk[i]) * N + n0 + bng[i] * 4);
                }
            }
#pragma unroll
            for (int kk = 0; kk < 16; kk++) {
                float4 a0 = *(float4*)&As[cur][kk][ty * 8];
                float4 a1 = *(float4*)&As[cur][kk][ty * 8 + 4];
                float4 b0 = *(float4*)&Bs[cur][kk][tx * 8];
                float4 b1 = *(float4*)&Bs[cur][kk][tx * 8 + 4];
                ull bp0 = pk2(b0.x, b0.y), bp1 = pk2(b0.z, b0.w);
                ull bp2 = pk2(b1.x, b1.y), bp3 = pk2(b1.z, b1.w);
                float av[8] = {a0.x, a0.y, a0.z, a0.w, a1.x, a1.y, a1.z, a1.w};
#pragma unroll
                for (int i = 0; i < 8; i++) {
                    ull ad = pk2(av[i], av[i]);
                    ffma2(acc[i][0], ad, bp0);
                    ffma2(acc[i][1], ad, bp1);
                    ffma2(acc[i][2], ad, bp2);
                    ffma2(acc[i][3], ad, bp3);
                }
            }
            cur ^= 1;
        }
#pragma unroll
        for (int i = 0; i < 8; i++) {
            int row = m0 + ty * 8 + i;
            float2 v0 = up2(acc[i][0]), v1 = up2(acc[i][1]);
            float2 v2 = up2(acc[i][2]), v3 = up2(acc[i][3]);
            float4 o0 = make_float4(v0.x, v0.y, v1.x, v1.y);
            float4 o1 = make_float4(v2.x, v2.y, v3.x, v3.y);
            *(float4*)(C + (size_t)row * N + n0 + tx * 8) = o0;
            *(float4*)(C + (size_t)row * N + n0 + tx * 8 + 4) = o1;
        }
        __threadfence();
        __syncthreads();
        if (tid == 0) atomicAdd(&g_tfl[(mt >> 3) * 4 + ((mt & 7) >> 1)], 1);
        return;
    }

    if (bid >= 296) {
        // ================= gemm_tn role (K-split 4, rn applied to A) ========
        float (*As)[16][128] = (float (*)[16][128])smraw;
        float (*Bs)[16][128] = (float (*)[16][128])(smraw + 2 * 16 * 128 * 4);
        const int gid = bid - 296;
        const int nt = gid & 1, bks = (gid >> 1) & 31, mchunk = gid >> 6;
        const int b = bks >> 2, ks = bks & 3;
        const int kbeg = ks * (L_ / 4), kend = kbeg + (L_ / 4);
        const int N = 256, lda = L_;
        const float* Ab = graph + (size_t)b * L_ * L_;
        const float* Bb0 = tq0 + (size_t)b * L_ * U_;
        const float* Bb1 = tq1 + (size_t)b * L_ * U_;
        const float* rnb = rn + (size_t)b * L_;
        float* Cs = (ks == 0) ? xq0 : (ks == 1) ? xq1 : (ks == 2) ? xq2 : xq3;
        float* C = Cs + (size_t)b * L_ * U_;
        const int m0 = mchunk * 128, n0 = nt * 128;
        const int tx = tid & 15, ty = tid >> 4;

        // wait for t (count 8) and rn (count 1) for this (b, ks)
        {
            volatile int* tf = &g_tfl[b * 4 + ks];
            volatile int* nf = &g_nfl[b * 4 + ks];
            if (tid == 0) {
                while (*tf < 8) { }
                while (*nf < 1) { }
            }
            __syncthreads();
            __threadfence();
        }

        ull acc[8][4];
#pragma unroll
        for (int i = 0; i < 8; i++)
#pragma unroll
            for (int j = 0; j < 4; j++) acc[i][j] = 0ull;

        int kk_[2], g_[2];
#pragma unroll
        for (int i = 0; i < 2; i++) {
            int f4 = tid + i * 256;
            kk_[i] = f4 >> 5; g_[i] = f4 & 31;
        }

        float4 ra[2], rb0[2], rb1[2];
        float rsc[2];
#pragma unroll
        for (int i = 0; i < 2; i++) {
            size_t ko = (size_t)(kbeg + kk_[i]);
            ra[i] = *(const float4*)(Ab + ko * lda + m0 + g_[i] * 4);
            rb0[i] = *(const float4*)(Bb0 + ko * N + n0 + g_[i] * 4);
            rb1[i] = *(const float4*)(Bb1 + ko * N + n0 + g_[i] * 4);
            rsc[i] = rnb[ko];
        }

        int cur = 0;
        for (int k0 = kbeg; k0 < kend; k0 += 16) {
#pragma unroll
            for (int i = 0; i < 2; i++) {
                float r = rsc[i];
                float4 sa = make_float4(ra[i].x * r, ra[i].y * r,
                                        ra[i].z * r, ra[i].w * r);
                *(float4*)&As[cur][kk_[i]][g_[i] * 4] = sa;
                float4 s = make_float4(rb0[i].x + rb1[i].x, rb0[i].y + rb1[i].y,
                                       rb0[i].z + rb1[i].z, rb0[i].w + rb1[i].w);
                *(float4*)&Bs[cur][kk_[i]][g_[i] * 4] = s;
            }
            __syncthreads();
            if (k0 + 16 < kend) {
#pragma unroll
                for (int i = 0; i < 2; i++) {
                    size_t ko = (size_t)(k0 + 16 + kk_[i]);
                    ra[i] = *(const float4*)(Ab + ko * lda + m0 + g_[i] * 4);
                    rb0[i] = *(const float4*)(Bb0 + ko * N + n0 + g_[i] * 4);
                    rb1[i] = *(const float4*)(Bb1 + ko * N + n0 + g_[i] * 4);
                    rsc[i] = rnb[ko];
                }
            }
#pragma unroll
            for (int kk = 0; kk < 16; kk++) {
                float4 a0 = *(float4*)&As[cur][kk][ty * 8];
                float4 a1 = *(float4*)&As[cur][kk][ty * 8 + 4];
                float4 b0 = *(float4*)&Bs[cur][kk][tx * 8];
                float4 b1 = *(float4*)&Bs[cur][kk][tx * 8 + 4];
                ull bp0 = pk2(b0.x, b0.y), bp1 = pk2(b0.z, b0.w);
                ull bp2 = pk2(b1.x, b1.y), bp3 = pk2(b1.z, b1.w);
                float av[8] = {a0.x, a0.y, a0.z, a0.w, a1.x, a1.y, a1.z, a1.w};
#pragma unroll
                for (int i = 0; i < 8; i++) {
                    ull ad = pk2(av[i], av[i]);
                    ffma2(acc[i][0], ad, bp0);
                    ffma2(acc[i][1], ad, bp1);
                    ffma2(acc[i][2], ad, bp2);
                    ffma2(acc[i][3], ad, bp3);
                }
            }
            cur ^= 1;
        }
#pragma unroll
        for (int i = 0; i < 8; i++) {
            int row = m0 + ty * 8 + i;
            float2 v0 = up2(acc[i][0]), v1 = up2(acc[i][1]);
            float2 v2 = up2(acc[i][2]), v3 = up2(acc[i][3]);
            float4 o0 = make_float4(v0.x, v0.y, v1.x, v1.y);
            float4 o1 = make_float4(v2.x, v2.y, v3.x, v3.y);
            *(float4*)(C + (size_t)row * N + n0 + tx * 8) = o0;
            *(float4*)(C + (size_t)row * N + n0 + tx * 8 + 4) = o1;
        }
        __threadfence();
        __syncthreads();
        if (tid == 0) atomicAdd(&g_flags[b][mchunk], 1);
        return;
    }

    // ================= scan role (R9 skeleton; ws packed as ulonglong2) =====
    ulonglong2* ws2 = (ulonglong2*)smraw;               // 48 KB weights
    float* part = (float*)(smraw + OFF_PART);           // 4 KB partials
    float* hbuf = (float*)(smraw + OFF_HB);             // 2 KB h (double buf)

    const int b = bid;
    const int w = tid >> 5, l = tid & 31;
    const int ks = w >> 1, oh = w & 1;
    const int u0 = oh * 128 + l * 4;

    // ws2[(ps*2 + jp)*256 + owner_tid] = { pair for out u0+2jp, pair for u0+2jp+1 }
    for (int idx = tid; idx < WS2_ELEMS; idx += 256) {
        int e = idx >> 8;
        int r = idx & 255;
        int ps = e >> 1, jp = e & 1;
        int wf = r >> 5, lf = r & 31;
        int ksf = wf >> 1, ohf = wf & 1;
        int uf = ohf * 128 + lf * 4 + 2 * jp;
        int kf = ksf * 64 + 2 * (RF_PAIRS + ps);
        ulonglong2 v;
        v.x = pk2(Wh[kf * U_ + uf], Wh[(kf + 1) * U_ + uf]);
        v.y = pk2(Wh[kf * U_ + uf + 1], Wh[(kf + 1) * U_ + uf + 1]);
        ws2[idx] = v;
    }

    ull wreg[4][RF_PAIRS];
#pragma unroll
    for (int j = 0; j < 4; j++)
#pragma unroll
        for (int p = 0; p < RF_PAIRS; p++) {
            int k = ks * 64 + 2 * p;
            wreg[j][p] = pk2(Wh[k * U_ + u0 + j], Wh[(k + 1) * U_ + u0 + j]);
        }

    hbuf[tid] = 0.f;
    hbuf[256 + tid] = 0.f;
    const float bv = bias[tid];
    __syncthreads();

    const float* xp0 = xq0 + (size_t)b * L_ * U_ + tid;
    const float* xp1 = xq1 + (size_t)b * L_ * U_ + tid;
    const float* xp2 = xq2 + (size_t)b * L_ * U_ + tid;
    const float* xp3 = xq3 + (size_t)b * L_ * U_ + tid;
    float* op = out + (size_t)b * L_ * U_ + tid;
    int cur = 0;

    const ulonglong2* wp = ws2 + tid;
    volatile int* flagp = &g_flags[b][0];

    for (int c = 0; c < NCHUNK; c++) {
        if (tid == 0) {
            while (flagp[c] < 8) { }
        }
        __syncthreads();
        __threadfence();  // acquire: pair with producers' release fences

        for (int si = 0; si < CHUNK; si++) {
            int s = c * CHUNK + si;
            size_t xo = (size_t)s * U_;
            float xa = xp0[xo], xb = xp1[xo], xc = xp2[xo], xd = xp3[xo];

            const ulonglong2* hp2 = (const ulonglong2*)(hbuf + cur * 256 + ks * 64);
            ull a0 = 0ull, a1 = 0ull, a2 = 0ull, a3 = 0ull;
            // SMEM-weight FMAs first (R9 win), LDS.128 packed (R7 layout)
#pragma unroll
            for (int qq = 0; qq < 3; qq++) { // pairs 26..31
                ulonglong2 hv = hp2[13 + qq];
                int ps0 = 2 * qq, ps1 = 2 * qq + 1;
                ulonglong2 W0a = wp[(ps0 * 2 + 0) * 256];
                ulonglong2 W0b = wp[(ps0 * 2 + 1) * 256];
                ffma2(a0, hv.x, W0a.x);
                ffma2(a1, hv.x, W0a.y);
                ffma2(a2, hv.x, W0b.x);
                ffma2(a3, hv.x, W0b.y);
                ulonglong2 W1a = wp[(ps1 * 2 + 0) * 256];
                ulonglong2 W1b = wp[(ps1 * 2 + 1) * 256];
                ffma2(a0, hv.y, W1a.x);
                ffma2(a1, hv.y, W1a.y);
                ffma2(a2, hv.y, W1b.x);
                ffma2(a3, hv.y, W1b.y);
            }
#pragma unroll
            for (int q = 0; q < 13; q++) {   // pairs 0..25 (RF)
                ulonglong2 hv = hp2[q];
                ffma2(a0, hv.x, wreg[0][2 * q]);
                ffma2(a1, hv.x, wreg[1][2 * q]);
                ffma2(a2, hv.x, wreg[2][2 * q]);
                ffma2(a3, hv.x, wreg[3][2 * q]);
                ffma2(a0, hv.y, wreg[0][2 * q + 1]);
                ffma2(a1, hv.y, wreg[1][2 * q + 1]);
                ffma2(a2, hv.y, wreg[2][2 * q + 1]);
                ffma2(a3, hv.y, wreg[3][2 * q + 1]);
            }
            float2 v0 = up2(a0), v1 = up2(a1), v2 = up2(a2), v3 = up2(a3);
            float4 pr = make_float4(v0.x + v0.y, v1.x + v1.y,
                                    v2.x + v2.y, v3.x + v3.y);
            float xv = ((xa + xb) + (xc + xd)) + bv;
            *(float4*)&part[ks * 256 + u0] = pr;
            __syncthreads();

            float z = part[tid] + part[256 + tid] + part[512 + tid] +
                      part[768 + tid] + xv;
            float h = fast_tanh(z);
            hbuf[(cur ^ 1) * 256 + tid] = h;
            op[xo] = h;
            cur ^= 1;
            __syncthreads();
        }
    }
}

// ---------------- launch --------------------------------------------------
extern "C" void kernel_launch(void* const* d_in, const int* in_sizes, int n_in,
                              void* d_out, int out_size) {
    const float* seq = (const float*)d_in[0];    // (8,1024,256)
    const float* graph = (const float*)d_in[1];  // (8,1024,1024)
    const float* E = (const float*)d_in[2];      // (256,256)
    const float* Wx = (const float*)d_in[3];     // (256,256)
    const float* Wh = (const float*)d_in[4];     // (256,256)
    const float* bias = (const float*)d_in[5];   // (256,)
    float* out = (float*)d_out;                  // (8,1024,256)

    float *ew, *rn, *t0, *t1, *x0, *x1, *x2, *x3;
    cudaGetSymbolAddress((void**)&ew, g_EW);
    cudaGetSymbolAddress((void**)&rn, g_rnorm);
    cudaGetSymbolAddress((void**)&t0, g_tp0);
    cudaGetSymbolAddress((void**)&t1, g_tp1);
    cudaGetSymbolAddress((void**)&x0, g_xp0);
    cudaGetSymbolAddress((void**)&x1, g_xp1);
    cudaGetSymbolAddress((void**)&x2, g_xp2);
    cudaGetSymbolAddress((void**)&x3, g_xp3);

    zero_flags_kernel<<<1, 128>>>();
    // EW = E @ Wx (tiny, stays a preamble kernel)
    gemm_nn<<<dim3(2, 2), 256>>>(E, Wx, ew, 256, nullptr);
    // everything else: one fused pipeline kernel
    cudaFuncSetAttribute(fused_kernel, cudaFuncAttributeMaxDynamicSharedMemorySize,
                         SCAN_SMEM_BYTES);
    fused_kernel<<<808, 256, SCAN_SMEM_BYTES>>>(graph, seq, ew, Wh, bias, rn,
                                                t0, t1, x0, x1, x2, x3, out);
}